// round 14
// baseline (speedup 1.0000x reference)
#include <cuda_runtime.h>
#include <cstdint>

#define ALPHA 0.2f

#define NB 16
#define NN 1024
#define NF 256

// Scratch (device globals: allocation-free rule)
__device__ float g_h[NB * NN * NF];           // 16 MB: h = x @ W (tf32-pre-rounded)
__device__ float g_el[NB * NN];
__device__ float g_er[NB * NN];
__device__ float g_eel[NB * NN];              // exp(el)
__device__ float g_eel2[NB * NN];             // exp(ALPHA*el)
__device__ float g_eer[NB * NN];              // exp(er)
__device__ float g_eer2[NB * NN];             // exp(ALPHA*er)
__device__ float g_wa[2 * NF];                // W @ a_l, W @ a_r

// ---------------------------------------------------------------------------
// helpers
// ---------------------------------------------------------------------------
__device__ __forceinline__ uint32_t f2tf32(float f) {
    uint32_t r;
    asm("cvt.rna.tf32.f32 %0, %1;" : "=r"(r) : "f"(f));
    return r;
}
__device__ __forceinline__ void cpasync16(uint32_t dst, const void* src) {
    asm volatile("cp.async.cg.shared.global [%0], [%1], 16;" :: "r"(dst), "l"(src));
}

// ---- h = x@W GEMM smem geometry ----
#define AS_STRIDE 36
#define BS_STRIDE 136
#define AS_TILE (128 * AS_STRIDE)      // 4608
#define BS_TILE (32 * BS_STRIDE)       // 4352
#define G1_STG (AS_TILE + BS_TILE)
#define G1_SMEM_BYTES (2 * G1_STG * 4)             // 71680

// ---- fused GEMM smem geometry: 128x256 tile, 512 thr, 3-slot B/adj ring ----
#define FBS_STRIDE 264
#define FBS_TILE (32 * FBS_STRIDE)     // 8448
#define ADJ_STRIDE 32
#define ADJ_TILE (128 * ADJ_STRIDE)    // 4096
#define FU_WORDS (2 * AS_TILE + 3 * FBS_TILE + 3 * ADJ_TILE + 128)
#define FU_SMEM_BYTES (FU_WORDS * 4)   // 187904

// ---------------------------------------------------------------------------
// GEMM1: h = x@W, tf32 mma.sync, cp.async double-buffered.
// Epilogue stores tf32-PRE-ROUNDED values (fused kernel reads raw uints).
// ---------------------------------------------------------------------------
__global__ __launch_bounds__(256, 2) void mma_gemm_kernel(
    const float* __restrict__ A, const float* __restrict__ B,
    float* __restrict__ C, int K)
{
    extern __shared__ float smem[];

    const int lda = K;
    const int ldb = NF;
    const int ldc = NF;

    const int bm = blockIdx.x * 128;
    const int bn = blockIdx.y * 128;
    const int tid = threadIdx.x;
    const int warp = tid >> 5;
    const int lane = tid & 31;
    const int wm = warp >> 2;
    const int wn = warp & 3;
    const int g = lane >> 2;
    const int t = lane & 3;

    int a_row[4], a_c4[4], b_row[4], b_c4[4];
#pragma unroll
    for (int j = 0; j < 4; j++) {
        int i = tid + j * 256;
        a_row[j] = i >> 3;  a_c4[j] = (i & 7) * 4;
        b_row[j] = i >> 5;  b_c4[j] = (i & 31) * 4;
    }

    uint32_t smem_u32 = (uint32_t)__cvta_generic_to_shared((void*)smem);
    const int niter = K / 32;

    auto issue_stage = [&](int s, int k0) {
        uint32_t as_base = smem_u32 + (uint32_t)(s * G1_STG) * 4u;
        uint32_t bs_base = as_base + (uint32_t)AS_TILE * 4u;
#pragma unroll
        for (int j = 0; j < 4; j++)
            cpasync16(as_base + (uint32_t)(a_row[j] * AS_STRIDE + a_c4[j]) * 4u,
                      &A[(size_t)(bm + a_row[j]) * lda + k0 + a_c4[j]]);
#pragma unroll
        for (int j = 0; j < 4; j++)
            cpasync16(bs_base + (uint32_t)(b_row[j] * BS_STRIDE + b_c4[j]) * 4u,
                      &B[(size_t)(k0 + b_row[j]) * ldb + bn + b_c4[j]]);
        asm volatile("cp.async.commit_group;");
    };

    float acc[4][4][4];
#pragma unroll
    for (int mi = 0; mi < 4; mi++)
#pragma unroll
        for (int ni = 0; ni < 4; ni++)
#pragma unroll
            for (int r = 0; r < 4; r++) acc[mi][ni][r] = 0.f;

    issue_stage(0, 0);

    for (int it = 0; it < niter; it++) {
        if (it + 1 < niter) {
            issue_stage((it + 1) & 1, (it + 1) * 32);
            asm volatile("cp.async.wait_group 1;");
        } else {
            asm volatile("cp.async.wait_group 0;");
        }
        __syncthreads();

        const float* As = smem + (it & 1) * G1_STG;
        const float* Bs = As + AS_TILE;

#pragma unroll
        for (int kc = 0; kc < 4; kc++) {
            const int kk = kc * 8;
            uint32_t af[4][4], bf[4][2];
#pragma unroll
            for (int mi = 0; mi < 4; mi++) {
                int m0 = wm * 64 + mi * 16;
                af[mi][0] = f2tf32(As[(m0 + g) * AS_STRIDE + kk + t]);
                af[mi][1] = f2tf32(As[(m0 + g + 8) * AS_STRIDE + kk + t]);
                af[mi][2] = f2tf32(As[(m0 + g) * AS_STRIDE + kk + t + 4]);
                af[mi][3] = f2tf32(As[(m0 + g + 8) * AS_STRIDE + kk + t + 4]);
            }
#pragma unroll
            for (int ni = 0; ni < 4; ni++) {
                int n0 = wn * 32 + ni * 8;
                bf[ni][0] = f2tf32(Bs[(kk + t) * BS_STRIDE + n0 + g]);
                bf[ni][1] = f2tf32(Bs[(kk + t + 4) * BS_STRIDE + n0 + g]);
            }
#pragma unroll
            for (int mi = 0; mi < 4; mi++)
#pragma unroll
                for (int ni = 0; ni < 4; ni++) {
                    asm volatile(
                        "mma.sync.aligned.m16n8k8.row.col.f32.tf32.tf32.f32 "
                        "{%0,%1,%2,%3}, {%4,%5,%6,%7}, {%8,%9}, {%0,%1,%2,%3};"
                        : "+f"(acc[mi][ni][0]), "+f"(acc[mi][ni][1]),
                          "+f"(acc[mi][ni][2]), "+f"(acc[mi][ni][3])
                        : "r"(af[mi][0]), "r"(af[mi][1]), "r"(af[mi][2]), "r"(af[mi][3]),
                          "r"(bf[ni][0]), "r"(bf[ni][1]));
                }
        }
        __syncthreads();
    }

    // store tf32-pre-rounded h
#pragma unroll
    for (int mi = 0; mi < 4; mi++) {
#pragma unroll
        for (int ni = 0; ni < 4; ni++) {
            int row0 = bm + wm * 64 + mi * 16 + g;
            int col = bn + wn * 32 + ni * 8 + t * 2;
            float2 v0 = make_float2(__uint_as_float(f2tf32(acc[mi][ni][0])),
                                    __uint_as_float(f2tf32(acc[mi][ni][1])));
            float2 v1 = make_float2(__uint_as_float(f2tf32(acc[mi][ni][2])),
                                    __uint_as_float(f2tf32(acc[mi][ni][3])));
            *(float2*)&C[(size_t)row0 * ldc + col] = v0;
            *(float2*)&C[(size_t)(row0 + 8) * ldc + col] = v1;
        }
    }
}

// ---------------------------------------------------------------------------
// FUSED attention GEMM, 128x256 tile, 512 threads (16 warps, 2x8).
// ONE barrier per k-iter; fill of As[it+1] sandwiched between the two MMA
// halves of iter it so it overlaps tensor-pipe drain. 3-slot B/adj ring
// (2 cp.async groups in flight). B (h) is tf32-pre-rounded: no cvt on frags.
// ---------------------------------------------------------------------------
__global__ __launch_bounds__(512, 1) void fused_attn_gemm_kernel(
    const int* __restrict__ adjg, const float* __restrict__ Hg,
    float* __restrict__ Cg)
{
    extern __shared__ float smem[];
    float* As_base = smem;                                   // 2 x 128x36
    float* Bs_base = smem + 2 * AS_TILE;                     // 3 x 32x264
    int* adj_base = (int*)(smem + 2 * AS_TILE + 3 * FBS_TILE);   // 3 x 128x32
    float* srow = (float*)(adj_base + 3 * ADJ_TILE);         // 128

    const int b = blockIdx.z;
    const int* Aj = adjg + (size_t)b * NN * NN;
    const float* B = Hg + (size_t)b * NN * NF;
    float* C = Cg + (size_t)b * NN * NF;
    const float* er_b = g_er + b * NN;
    const float* eer_b = g_eer + b * NN;
    const float* eer2_b = g_eer2 + b * NN;

    const int bm = blockIdx.x * 128;
    const int tid = threadIdx.x;
    const int warp = tid >> 5;
    const int lane = tid & 31;
    const int wm = warp >> 3;        // 0..1 (M)
    const int wn = warp & 7;         // 0..7 (N)
    const int g = lane >> 2;
    const int t = lane & 3;

    // A/adj fill coords: rows ar, ar+64; cols ac4..ac4+3 (thread-owned)
    const int ar = tid >> 3;
    const int ac4 = (tid & 7) * 4;
    // B fill coords: 2048 vec4 / 512 = 4 each
    int b_row[4], b_c4[4];
#pragma unroll
    for (int j = 0; j < 4; j++) {
        int i = tid + j * 512;
        b_row[j] = i >> 6;  b_c4[j] = (i & 63) * 4;
    }

    // loop-invariant per-row values
    float elr[2], eelr[2], eel2r[2];
#pragma unroll
    for (int j = 0; j < 2; j++) {
        int row = bm + ar + j * 64;
        elr[j] = g_el[b * NN + row];
        eelr[j] = g_eel[b * NN + row];
        eel2r[j] = g_eel2[b * NN + row];
    }
    float psum[2] = {0.f, 0.f};

    uint32_t adj_u32 = (uint32_t)__cvta_generic_to_shared((void*)adj_base);
    uint32_t bs_u32 = (uint32_t)__cvta_generic_to_shared((void*)Bs_base);

    auto issue_cp = [&](int slot, int k0) {
        uint32_t aj = adj_u32 + (uint32_t)(slot * ADJ_TILE) * 4u;
        uint32_t bs = bs_u32 + (uint32_t)(slot * FBS_TILE) * 4u;
#pragma unroll
        for (int j = 0; j < 2; j++) {
            int row = ar + j * 64;
            cpasync16(aj + (uint32_t)(row * ADJ_STRIDE + ac4) * 4u,
                      Aj + (size_t)(bm + row) * NN + k0 + ac4);
        }
#pragma unroll
        for (int j = 0; j < 4; j++)
            cpasync16(bs + (uint32_t)(b_row[j] * FBS_STRIDE + b_c4[j]) * 4u,
                      &B[(size_t)(k0 + b_row[j]) * NF + b_c4[j]]);
        asm volatile("cp.async.commit_group;");
    };

    // fill As[dst] with p~ for k-range [k1, k1+32). adj data is thread-owned.
    auto fill_A = [&](int dst, int slot, int k1) {
        uint32_t* As = (uint32_t*)(As_base + dst * AS_TILE);
        const int* adjS = adj_base + slot * ADJ_TILE;
#pragma unroll
        for (int j = 0; j < 2; j++) {
            int row = ar + j * 64;
            int4 av = *(const int4*)&adjS[row * ADJ_STRIDE + ac4];
            float4 er4 = *(const float4*)&er_b[k1 + ac4];
            float4 ee4 = *(const float4*)&eer_b[k1 + ac4];
            float4 ee24 = *(const float4*)&eer2_b[k1 + ac4];
            float el_ = elr[j], ee_ = eelr[j], ee2_ = eel2r[j];
            bool s0 = (el_ + er4.x) > 0.f;
            bool s1 = (el_ + er4.y) > 0.f;
            bool s2 = (el_ + er4.z) > 0.f;
            bool s3 = (el_ + er4.w) > 0.f;
            float p0 = av.x > 0 ? (s0 ? ee_ * ee4.x : ee2_ * ee24.x) : 0.f;
            float p1 = av.y > 0 ? (s1 ? ee_ * ee4.y : ee2_ * ee24.y) : 0.f;
            float p2 = av.z > 0 ? (s2 ? ee_ * ee4.z : ee2_ * ee24.z) : 0.f;
            float p3 = av.w > 0 ? (s3 ? ee_ * ee4.w : ee2_ * ee24.w) : 0.f;
            uint32_t u0 = f2tf32(p0), u1 = f2tf32(p1);
            uint32_t u2 = f2tf32(p2), u3 = f2tf32(p3);
            *(uint4*)&As[row * AS_STRIDE + ac4] = make_uint4(u0, u1, u2, u3);
            psum[j] += __uint_as_float(u0) + __uint_as_float(u1) +
                       __uint_as_float(u2) + __uint_as_float(u3);
        }
    };

    float acc[4][4][4];
#pragma unroll
    for (int mi = 0; mi < 4; mi++)
#pragma unroll
        for (int ni = 0; ni < 4; ni++)
#pragma unroll
            for (int r = 0; r < 4; r++) acc[mi][ni][r] = 0.f;

    const int niter = NN / 32;     // 32

    // prologue
    issue_cp(0, 0);
    issue_cp(1, 32);
    asm volatile("cp.async.wait_group 1;");   // group 0 done (adj[0] thread-local)
    fill_A(0, 0, 0);

    for (int it = 0; it < niter; it++) {
        const int s = it & 1;
        const int bslot = it % 3;

        if (it + 2 < niter) {
            issue_cp((it + 2) % 3, (it + 2) * 32);
            asm volatile("cp.async.wait_group 1;");   // group(it+1) done
        } else {
            asm volatile("cp.async.wait_group 0;");
        }
        __syncthreads();   // As[s] + Bs[bslot] visible; MMA(it-1) on As[s^1] done

        const uint32_t* As = (const uint32_t*)(As_base + s * AS_TILE);
        const uint32_t* Bs = (const uint32_t*)(Bs_base + bslot * FBS_TILE);

        // ---- MMA half 1: kc = 0,1 ----
#pragma unroll
        for (int kc = 0; kc < 2; kc++) {
            const int kk = kc * 8;
            uint32_t af[4][4], bf[4][2];
#pragma unroll
            for (int mi = 0; mi < 4; mi++) {
                int m0 = wm * 64 + mi * 16;
                af[mi][0] = As[(m0 + g) * AS_STRIDE + kk + t];
                af[mi][1] = As[(m0 + g + 8) * AS_STRIDE + kk + t];
                af[mi][2] = As[(m0 + g) * AS_STRIDE + kk + t + 4];
                af[mi][3] = As[(m0 + g + 8) * AS_STRIDE + kk + t + 4];
            }
#pragma unroll
            for (int ni = 0; ni < 4; ni++) {
                int n0 = wn * 32 + ni * 8;
                bf[ni][0] = Bs[(kk + t) * FBS_STRIDE + n0 + g];
                bf[ni][1] = Bs[(kk + t + 4) * FBS_STRIDE + n0 + g];
            }
#pragma unroll
            for (int mi = 0; mi < 4; mi++)
#pragma unroll
                for (int ni = 0; ni < 4; ni++) {
                    asm volatile(
                        "mma.sync.aligned.m16n8k8.row.col.f32.tf32.tf32.f32 "
                        "{%0,%1,%2,%3}, {%4,%5,%6,%7}, {%8,%9}, {%0,%1,%2,%3};"
                        : "+f"(acc[mi][ni][0]), "+f"(acc[mi][ni][1]),
                          "+f"(acc[mi][ni][2]), "+f"(acc[mi][ni][3])
                        : "r"(af[mi][0]), "r"(af[mi][1]), "r"(af[mi][2]), "r"(af[mi][3]),
                          "r"(bf[ni][0]), "r"(bf[ni][1]));
                }
        }

        // ---- fill As for it+1 (other buffer) — overlaps tensor drain ----
        if (it + 1 < niter)
            fill_A(s ^ 1, (it + 1) % 3, (it + 1) * 32);

        // ---- MMA half 2: kc = 2,3 ----
#pragma unroll
        for (int kc = 2; kc < 4; kc++) {
            const int kk = kc * 8;
            uint32_t af[4][4], bf[4][2];
#pragma unroll
            for (int mi = 0; mi < 4; mi++) {
                int m0 = wm * 64 + mi * 16;
                af[mi][0] = As[(m0 + g) * AS_STRIDE + kk + t];
                af[mi][1] = As[(m0 + g + 8) * AS_STRIDE + kk + t];
                af[mi][2] = As[(m0 + g) * AS_STRIDE + kk + t + 4];
                af[mi][3] = As[(m0 + g + 8) * AS_STRIDE + kk + t + 4];
            }
#pragma unroll
            for (int ni = 0; ni < 4; ni++) {
                int n0 = wn * 32 + ni * 8;
                bf[ni][0] = Bs[(kk + t) * FBS_STRIDE + n0 + g];
                bf[ni][1] = Bs[(kk + t + 4) * FBS_STRIDE + n0 + g];
            }
#pragma unroll
            for (int mi = 0; mi < 4; mi++)
#pragma unroll
                for (int ni = 0; ni < 4; ni++) {
                    asm volatile(
                        "mma.sync.aligned.m16n8k8.row.col.f32.tf32.tf32.f32 "
                        "{%0,%1,%2,%3}, {%4,%5,%6,%7}, {%8,%9}, {%0,%1,%2,%3};"
                        : "+f"(acc[mi][ni][0]), "+f"(acc[mi][ni][1]),
                          "+f"(acc[mi][ni][2]), "+f"(acc[mi][ni][3])
                        : "r"(af[mi][0]), "r"(af[mi][1]), "r"(af[mi][2]), "r"(af[mi][3]),
                          "r"(bf[ni][0]), "r"(bf[ni][1]));
                }
        }
        __syncthreads();   // As[s^1] filled by all; done reading As[s]/Bs[bslot]
    }

    // Deterministic per-row sum: each As row filled by 8 consecutive lanes.
#pragma unroll
    for (int j = 0; j < 2; j++) {
        float v = psum[j];
        v += __shfl_xor_sync(0xffffffffu, v, 4);
        v += __shfl_xor_sync(0xffffffffu, v, 2);
        v += __shfl_xor_sync(0xffffffffu, v, 1);
        if ((lane & 7) == 0) srow[ar + j * 64] = v;
    }
    __syncthreads();

#pragma unroll
    for (int mi = 0; mi < 4; mi++) {
        int r0 = wm * 64 + mi * 16 + g;
        float inv0 = 1.0f / srow[r0];
        float inv8 = 1.0f / srow[r0 + 8];
#pragma unroll
        for (int ni = 0; ni < 4; ni++) {
            int col = wn * 32 + ni * 8 + t * 2;
            *(float2*)&C[(size_t)(bm + r0) * NF + col] =
                make_float2(acc[mi][ni][0] * inv0, acc[mi][ni][1] * inv0);
            *(float2*)&C[(size_t)(bm + r0 + 8) * NF + col] =
                make_float2(acc[mi][ni][2] * inv8, acc[mi][ni][3] * inv8);
        }
    }
}

// ---------------------------------------------------------------------------
// wa[sel][i] = sum_o W[i][o] * a[sel*256 + o]    (exact fp32, tiny)
// ---------------------------------------------------------------------------
__global__ __launch_bounds__(256) void wa_kernel(
    const float* __restrict__ W, const float* __restrict__ a)
{
    int i = blockIdx.x & 255;
    int sel = blockIdx.x >> 8;
    int tid = threadIdx.x;
    float v = W[(size_t)i * NF + tid] * a[sel * NF + tid];
#pragma unroll
    for (int off = 16; off > 0; off >>= 1)
        v += __shfl_xor_sync(0xffffffffu, v, off);
    __shared__ float s[8];
    if ((tid & 31) == 0) s[tid >> 5] = v;
    __syncthreads();
    if (tid == 0) {
        float acc = 0.f;
#pragma unroll
        for (int w = 0; w < 8; w++) acc += s[w];
        g_wa[sel * NF + i] = acc;
    }
}

// ---------------------------------------------------------------------------
// Warp-per-row: el/er = x . wa  (float4 loads) + exp precomputes.
// ---------------------------------------------------------------------------
__global__ __launch_bounds__(256) void rowdot_x_kernel(const float* __restrict__ x)
{
    int row = blockIdx.x * 8 + (threadIdx.x >> 5);
    int lane = threadIdx.x & 31;
    const float* xr = x + (size_t)row * NF;

    float l = 0.f, r = 0.f;
#pragma unroll
    for (int c = 0; c < 2; c++) {
        int idx = (lane + c * 32) * 4;
        float4 xv = *(const float4*)&xr[idx];
        float4 wl = *(const float4*)&g_wa[idx];
        float4 wr = *(const float4*)&g_wa[NF + idx];
        l += xv.x * wl.x + xv.y * wl.y + xv.z * wl.z + xv.w * wl.w;
        r += xv.x * wr.x + xv.y * wr.y + xv.z * wr.z + xv.w * wr.w;
    }
#pragma unroll
    for (int o = 16; o > 0; o >>= 1) {
        l += __shfl_xor_sync(0xffffffffu, l, o);
        r += __shfl_xor_sync(0xffffffffu, r, o);
    }
    if (lane == 0) {
        g_el[row] = l;
        g_er[row] = r;
        g_eel[row] = __expf(l);
        g_eel2[row] = __expf(ALPHA * l);
        g_eer[row] = __expf(r);
        g_eer2[row] = __expf(ALPHA * r);
    }
}

// ---------------------------------------------------------------------------
extern "C" void kernel_launch(void* const* d_in, const int* in_sizes, int n_in,
                              void* d_out, int out_size)
{
    const float* x   = (const float*)d_in[0];   // (16,1024,256) f32
    const int*   adj = (const int*)d_in[1];     // (16,1024,1024) i32
    const float* W   = (const float*)d_in[2];   // (256,256) f32
    const float* a   = (const float*)d_in[3];   // (512,1) f32
    float* out = (float*)d_out;                 // (16,1024,256) f32

    float* h;
    cudaGetSymbolAddress((void**)&h, g_h);

    cudaFuncSetAttribute(mma_gemm_kernel,
                         cudaFuncAttributeMaxDynamicSharedMemorySize, G1_SMEM_BYTES);
    cudaFuncSetAttribute(fused_attn_gemm_kernel,
                         cudaFuncAttributeMaxDynamicSharedMemorySize, FU_SMEM_BYTES);

    // 1) wa = W @ [a_l | a_r]   (exact)
    wa_kernel<<<512, 256>>>(W, a);
    // 2) el/er = x @ wa (+ exp precomputes, exact fp32)
    rowdot_x_kernel<<<(NB * NN) / 8, 256>>>(x);
    // 3) h = x @ W  (tf32 mma.sync; stores tf32-pre-rounded)
    {
        dim3 grid((NB * NN) / 128, NF / 128, 1);
        mma_gemm_kernel<<<grid, 256, G1_SMEM_BYTES>>>(x, W, h, NF);
    }
    // 4) out = softmax(mask(leaky(el+er))) @ h — fused, fill/MMA overlapped
    {
        dim3 grid(NN / 128, 1, NB);
        fused_attn_gemm_kernel<<<grid, 512, FU_SMEM_BYTES>>>(adj, h, out);
    }
}

// round 15
// speedup vs baseline: 1.6609x; 1.6609x over previous
#include <cuda_runtime.h>
#include <cuda_fp16.h>
#include <cstdint>

#define ALPHA 0.2f

#define NB 16
#define NN 1024
#define NF 256

// Scratch (device globals: allocation-free rule)
__device__ __half g_hT[NB * NF * NN];         // 8 MB: hT[b][n][m] = fp16(x@W)
__device__ float g_el[NB * NN];
__device__ float g_er[NB * NN];
__device__ float g_eel[NB * NN];              // exp(el)
__device__ float g_eel2[NB * NN];             // exp(ALPHA*el)
__device__ float g_eer[NB * NN];              // exp(er)
__device__ float g_eer2[NB * NN];             // exp(ALPHA*er)
__device__ float g_wa[2 * NF];                // W @ a_l, W @ a_r

// ---------------------------------------------------------------------------
// helpers
// ---------------------------------------------------------------------------
__device__ __forceinline__ uint32_t f2tf32(float f) {
    uint32_t r;
    asm("cvt.rna.tf32.f32 %0, %1;" : "=r"(r) : "f"(f));
    return r;
}
__device__ __forceinline__ void cpasync16(uint32_t dst, const void* src) {
    asm volatile("cp.async.cg.shared.global [%0], [%1], 16;" :: "r"(dst), "l"(src));
}

// ---- GEMM1 (h = x@W, tf32) smem geometry ----
#define AS_STRIDE 36
#define BS_STRIDE 136
#define AS_TILE (128 * AS_STRIDE)      // 4608 words
#define BS_TILE (32 * BS_STRIDE)       // 4352 words
#define G1_STG (AS_TILE + BS_TILE)
#define G1_SMEM_BYTES (2 * G1_STG * 4)             // 71680

// ---- fused fp16 GEMM smem geometry (bytes) ----
// A tile: 128 rows x 32 halves, stride 40 halves (80B)  -> 10240 B/stage
// B tile: 256 rows x 32 halves, stride 40 halves (80B)  -> 20480 B/stage
// adj   : 128 x 32 int                                  -> 16384 B/stage
#define FA_ROWSTRIDE 80
#define FA_BYTES (128 * FA_ROWSTRIDE)      // 10240
#define FB_ROWSTRIDE 80
#define FB_BYTES (256 * FB_ROWSTRIDE)      // 20480
#define FADJ_BYTES (128 * 32 * 4)          // 16384
#define OFF_FA 0
#define OFF_FB (2 * FA_BYTES)                       // 20480
#define OFF_FADJ (OFF_FB + 2 * FB_BYTES)            // 61440
#define OFF_SROW (OFF_FADJ + 2 * FADJ_BYTES)        // 94208
#define FU_SMEM_BYTES (OFF_SROW + 512)              // 94720

// ---------------------------------------------------------------------------
// GEMM1: h = x@W (tf32 mma.sync, cp.async double-buffered).
// Epilogue writes hT[b][n][m] in fp16 (transposed, for fused B-fragments).
// ---------------------------------------------------------------------------
__global__ __launch_bounds__(256, 2) void mma_gemm_kernel(
    const float* __restrict__ A, const float* __restrict__ B,
    __half* __restrict__ hT, int K)
{
    extern __shared__ float smem[];

    const int lda = K;
    const int ldb = NF;

    const int bm = blockIdx.x * 128;
    const int bn = blockIdx.y * 128;
    const int tid = threadIdx.x;
    const int warp = tid >> 5;
    const int lane = tid & 31;
    const int wm = warp >> 2;
    const int wn = warp & 3;
    const int g = lane >> 2;
    const int t = lane & 3;

    int a_row[4], a_c4[4], b_row[4], b_c4[4];
#pragma unroll
    for (int j = 0; j < 4; j++) {
        int i = tid + j * 256;
        a_row[j] = i >> 3;  a_c4[j] = (i & 7) * 4;
        b_row[j] = i >> 5;  b_c4[j] = (i & 31) * 4;
    }

    uint32_t smem_u32 = (uint32_t)__cvta_generic_to_shared((void*)smem);
    const int niter = K / 32;

    auto issue_stage = [&](int s, int k0) {
        uint32_t as_base = smem_u32 + (uint32_t)(s * G1_STG) * 4u;
        uint32_t bs_base = as_base + (uint32_t)AS_TILE * 4u;
#pragma unroll
        for (int j = 0; j < 4; j++)
            cpasync16(as_base + (uint32_t)(a_row[j] * AS_STRIDE + a_c4[j]) * 4u,
                      &A[(size_t)(bm + a_row[j]) * lda + k0 + a_c4[j]]);
#pragma unroll
        for (int j = 0; j < 4; j++)
            cpasync16(bs_base + (uint32_t)(b_row[j] * BS_STRIDE + b_c4[j]) * 4u,
                      &B[(size_t)(k0 + b_row[j]) * ldb + bn + b_c4[j]]);
        asm volatile("cp.async.commit_group;");
    };

    float acc[4][4][4];
#pragma unroll
    for (int mi = 0; mi < 4; mi++)
#pragma unroll
        for (int ni = 0; ni < 4; ni++)
#pragma unroll
            for (int r = 0; r < 4; r++) acc[mi][ni][r] = 0.f;

    issue_stage(0, 0);

    for (int it = 0; it < niter; it++) {
        if (it + 1 < niter) {
            issue_stage((it + 1) & 1, (it + 1) * 32);
            asm volatile("cp.async.wait_group 1;");
        } else {
            asm volatile("cp.async.wait_group 0;");
        }
        __syncthreads();

        const float* As = smem + (it & 1) * G1_STG;
        const float* Bs = As + AS_TILE;

#pragma unroll
        for (int kc = 0; kc < 4; kc++) {
            const int kk = kc * 8;
            uint32_t af[4][4], bf[4][2];
#pragma unroll
            for (int mi = 0; mi < 4; mi++) {
                int m0 = wm * 64 + mi * 16;
                af[mi][0] = f2tf32(As[(m0 + g) * AS_STRIDE + kk + t]);
                af[mi][1] = f2tf32(As[(m0 + g + 8) * AS_STRIDE + kk + t]);
                af[mi][2] = f2tf32(As[(m0 + g) * AS_STRIDE + kk + t + 4]);
                af[mi][3] = f2tf32(As[(m0 + g + 8) * AS_STRIDE + kk + t + 4]);
            }
#pragma unroll
            for (int ni = 0; ni < 4; ni++) {
                int n0 = wn * 32 + ni * 8;
                bf[ni][0] = f2tf32(Bs[(kk + t) * BS_STRIDE + n0 + g]);
                bf[ni][1] = f2tf32(Bs[(kk + t + 4) * BS_STRIDE + n0 + g]);
            }
#pragma unroll
            for (int mi = 0; mi < 4; mi++)
#pragma unroll
                for (int ni = 0; ni < 4; ni++) {
                    asm volatile(
                        "mma.sync.aligned.m16n8k8.row.col.f32.tf32.tf32.f32 "
                        "{%0,%1,%2,%3}, {%4,%5,%6,%7}, {%8,%9}, {%0,%1,%2,%3};"
                        : "+f"(acc[mi][ni][0]), "+f"(acc[mi][ni][1]),
                          "+f"(acc[mi][ni][2]), "+f"(acc[mi][ni][3])
                        : "r"(af[mi][0]), "r"(af[mi][1]), "r"(af[mi][2]), "r"(af[mi][3]),
                          "r"(bf[ni][0]), "r"(bf[ni][1]));
                }
        }
        __syncthreads();
    }

    // Epilogue: hT[b][n][m] = fp16(acc)
#pragma unroll
    for (int mi = 0; mi < 4; mi++) {
#pragma unroll
        for (int ni = 0; ni < 4; ni++) {
            int row0 = bm + wm * 64 + mi * 16 + g;
            int col = bn + wn * 32 + ni * 8 + t * 2;
            int bi = row0 >> 10, m = row0 & 1023;
            __half* p = hT + ((size_t)bi * NF + col) * NN + m;
            p[0]       = __float2half_rn(acc[mi][ni][0]);
            p[NN]      = __float2half_rn(acc[mi][ni][1]);
            p[8]       = __float2half_rn(acc[mi][ni][2]);
            p[NN + 8]  = __float2half_rn(acc[mi][ni][3]);
        }
    }
}

// ---------------------------------------------------------------------------
// FUSED attention GEMM, fp16 mma.m16n8k16, 128x256 tile, 512 threads.
// A = p~ (unnormalized softmax numerators) fp16, built in smem.
// B = hT tiles (n-major rows, k contiguous) via cp.async.
// R12 control flow: double buffer, two bars/iter.
// ---------------------------------------------------------------------------
__global__ __launch_bounds__(512, 1) void fused_attn_gemm_kernel(
    const int* __restrict__ adjg, const __half* __restrict__ hTg,
    float* __restrict__ Cg)
{
    extern __shared__ char smc[];
    uint32_t sb = (uint32_t)__cvta_generic_to_shared((void*)smc);
    float* srow = (float*)(smc + OFF_SROW);

    const int b = blockIdx.z;
    const int* Aj = adjg + (size_t)b * NN * NN;
    const __half* hTb = hTg + (size_t)b * NF * NN;
    float* C = Cg + (size_t)b * NN * NF;
    const float* er_b = g_er + b * NN;
    const float* eer_b = g_eer + b * NN;
    const float* eer2_b = g_eer2 + b * NN;

    const int bm = blockIdx.x * 128;
    const int tid = threadIdx.x;
    const int warp = tid >> 5;
    const int lane = tid & 31;
    const int wm = warp >> 3;        // 0..1 (M)
    const int wn = warp & 7;         // 0..7 (N)
    const int g = lane >> 2;
    const int t = lane & 3;

    // A/adj fill coords: rows ar, ar+64; k-cols ac4..ac4+3
    const int ar = tid >> 3;
    const int ac4 = (tid & 7) * 4;
    // B fill coords: 1024 chunks of 16B / 512 threads = 2 each
    int bn_row[2], bn_ch[2];
#pragma unroll
    for (int j = 0; j < 2; j++) {
        int i = tid + j * 512;
        bn_row[j] = i >> 2;  bn_ch[j] = i & 3;
    }

    float elr[2], eelr[2], eel2r[2];
#pragma unroll
    for (int j = 0; j < 2; j++) {
        int row = bm + ar + j * 64;
        elr[j] = g_el[b * NN + row];
        eelr[j] = g_eel[b * NN + row];
        eel2r[j] = g_eel2[b * NN + row];
    }
    float psum[2] = {0.f, 0.f};

    auto issue_cp = [&](int s, int k0) {
        uint32_t aj = sb + OFF_FADJ + (uint32_t)(s * FADJ_BYTES);
#pragma unroll
        for (int j = 0; j < 2; j++) {
            int row = ar + j * 64;
            cpasync16(aj + (uint32_t)(row * 32 + ac4) * 4u,
                      Aj + (size_t)(bm + row) * NN + k0 + ac4);
        }
        uint32_t bs = sb + OFF_FB + (uint32_t)(s * FB_BYTES);
#pragma unroll
        for (int j = 0; j < 2; j++)
            cpasync16(bs + (uint32_t)(bn_row[j] * FB_ROWSTRIDE + bn_ch[j] * 16),
                      hTb + (size_t)bn_row[j] * NN + k0 + bn_ch[j] * 8);
        asm volatile("cp.async.commit_group;");
    };

    float acc[4][4][4];
#pragma unroll
    for (int mi = 0; mi < 4; mi++)
#pragma unroll
        for (int ni = 0; ni < 4; ni++)
#pragma unroll
            for (int r = 0; r < 4; r++) acc[mi][ni][r] = 0.f;

    issue_cp(0, 0);

    const int niter = NN / 32;     // 32
    for (int it = 0; it < niter; it++) {
        const int k0 = it * 32;
        const int s = it & 1;
        if (it + 1 < niter) {
            issue_cp(s ^ 1, (it + 1) * 32);
            asm volatile("cp.async.wait_group 1;");
        } else {
            asm volatile("cp.async.wait_group 0;");
        }
        __syncthreads();

        const int* adjS = (const int*)(smc + OFF_FADJ + s * FADJ_BYTES);
        char* AsB = smc + OFF_FA + s * FA_BYTES;

        // Fill A-tile: p~ = fp16(sel(adj, Eel*Eer | Eel2*Eer2, 0))
#pragma unroll
        for (int j = 0; j < 2; j++) {
            int row = ar + j * 64;
            int4 av = *(const int4*)&adjS[row * 32 + ac4];
            float4 er4 = *(const float4*)&er_b[k0 + ac4];
            float4 ee4 = *(const float4*)&eer_b[k0 + ac4];
            float4 ee24 = *(const float4*)&eer2_b[k0 + ac4];
            float el_ = elr[j], ee_ = eelr[j], ee2_ = eel2r[j];
            bool s0 = (el_ + er4.x) > 0.f;
            bool s1 = (el_ + er4.y) > 0.f;
            bool s2 = (el_ + er4.z) > 0.f;
            bool s3 = (el_ + er4.w) > 0.f;
            float p0 = av.x > 0 ? (s0 ? ee_ * ee4.x : ee2_ * ee24.x) : 0.f;
            float p1 = av.y > 0 ? (s1 ? ee_ * ee4.y : ee2_ * ee24.y) : 0.f;
            float p2 = av.z > 0 ? (s2 ? ee_ * ee4.z : ee2_ * ee24.z) : 0.f;
            float p3 = av.w > 0 ? (s3 ? ee_ * ee4.w : ee2_ * ee24.w) : 0.f;
            __half2 h01 = __floats2half2_rn(p0, p1);
            __half2 h23 = __floats2half2_rn(p2, p3);
            *(uint2*)(AsB + row * FA_ROWSTRIDE + ac4 * 2) =
                make_uint2(*(uint32_t*)&h01, *(uint32_t*)&h23);
            psum[j] += __low2float(h01) + __high2float(h01) +
                       __low2float(h23) + __high2float(h23);
        }
        __syncthreads();

        const uint32_t* As32 = (const uint32_t*)(smc + OFF_FA + s * FA_BYTES);
        const uint32_t* Bs32 = (const uint32_t*)(smc + OFF_FB + s * FB_BYTES);

        // 2 ksteps of K=16
#pragma unroll
        for (int ks = 0; ks < 2; ks++) {
            const int ko = ks * 8;     // uint32 offset within row (16 halves)
            uint32_t af[4][4], bf[4][2];
#pragma unroll
            for (int mi = 0; mi < 4; mi++) {
                int m0 = wm * 64 + mi * 16;
                int r0 = (m0 + g) * 20 + ko + t;
                int r8 = (m0 + g + 8) * 20 + ko + t;
                af[mi][0] = As32[r0];
                af[mi][1] = As32[r8];
                af[mi][2] = As32[r0 + 4];
                af[mi][3] = As32[r8 + 4];
            }
#pragma unroll
            for (int ni = 0; ni < 4; ni++) {
                int n0 = wn * 32 + ni * 8;
                int rb = (n0 + g) * 20 + ko + t;
                bf[ni][0] = Bs32[rb];
                bf[ni][1] = Bs32[rb + 4];
            }
#pragma unroll
            for (int mi = 0; mi < 4; mi++)
#pragma unroll
                for (int ni = 0; ni < 4; ni++) {
                    asm volatile(
                        "mma.sync.aligned.m16n8k16.row.col.f32.f16.f16.f32 "
                        "{%0,%1,%2,%3}, {%4,%5,%6,%7}, {%8,%9}, {%0,%1,%2,%3};"
                        : "+f"(acc[mi][ni][0]), "+f"(acc[mi][ni][1]),
                          "+f"(acc[mi][ni][2]), "+f"(acc[mi][ni][3])
                        : "r"(af[mi][0]), "r"(af[mi][1]), "r"(af[mi][2]), "r"(af[mi][3]),
                          "r"(bf[ni][0]), "r"(bf[ni][1]));
                }
        }
        __syncthreads();
    }

    // Deterministic per-row sum (8 lanes own each row's fill)
#pragma unroll
    for (int j = 0; j < 2; j++) {
        float v = psum[j];
        v += __shfl_xor_sync(0xffffffffu, v, 4);
        v += __shfl_xor_sync(0xffffffffu, v, 2);
        v += __shfl_xor_sync(0xffffffffu, v, 1);
        if ((lane & 7) == 0) srow[ar + j * 64] = v;
    }
    __syncthreads();

#pragma unroll
    for (int mi = 0; mi < 4; mi++) {
        int r0 = wm * 64 + mi * 16 + g;
        float inv0 = 1.0f / srow[r0];
        float inv8 = 1.0f / srow[r0 + 8];
#pragma unroll
        for (int ni = 0; ni < 4; ni++) {
            int col = wn * 32 + ni * 8 + t * 2;
            *(float2*)&C[(size_t)(bm + r0) * NF + col] =
                make_float2(acc[mi][ni][0] * inv0, acc[mi][ni][1] * inv0);
            *(float2*)&C[(size_t)(bm + r0 + 8) * NF + col] =
                make_float2(acc[mi][ni][2] * inv8, acc[mi][ni][3] * inv8);
        }
    }
}

// ---------------------------------------------------------------------------
// wa[sel][i] = sum_o W[i][o] * a[sel*256 + o]    (exact fp32, tiny)
// ---------------------------------------------------------------------------
__global__ __launch_bounds__(256) void wa_kernel(
    const float* __restrict__ W, const float* __restrict__ a)
{
    int i = blockIdx.x & 255;
    int sel = blockIdx.x >> 8;
    int tid = threadIdx.x;
    float v = W[(size_t)i * NF + tid] * a[sel * NF + tid];
#pragma unroll
    for (int off = 16; off > 0; off >>= 1)
        v += __shfl_xor_sync(0xffffffffu, v, off);
    __shared__ float s[8];
    if ((tid & 31) == 0) s[tid >> 5] = v;
    __syncthreads();
    if (tid == 0) {
        float acc = 0.f;
#pragma unroll
        for (int w = 0; w < 8; w++) acc += s[w];
        g_wa[sel * NF + i] = acc;
    }
}

// ---------------------------------------------------------------------------
// Warp-per-row: el/er = x . wa  (float4 loads) + exp precomputes.
// ---------------------------------------------------------------------------
__global__ __launch_bounds__(256) void rowdot_x_kernel(const float* __restrict__ x)
{
    int row = blockIdx.x * 8 + (threadIdx.x >> 5);
    int lane = threadIdx.x & 31;
    const float* xr = x + (size_t)row * NF;

    float l = 0.f, r = 0.f;
#pragma unroll
    for (int c = 0; c < 2; c++) {
        int idx = (lane + c * 32) * 4;
        float4 xv = *(const float4*)&xr[idx];
        float4 wl = *(const float4*)&g_wa[idx];
        float4 wr = *(const float4*)&g_wa[NF + idx];
        l += xv.x * wl.x + xv.y * wl.y + xv.z * wl.z + xv.w * wl.w;
        r += xv.x * wr.x + xv.y * wr.y + xv.z * wr.z + xv.w * wr.w;
    }
#pragma unroll
    for (int o = 16; o > 0; o >>= 1) {
        l += __shfl_xor_sync(0xffffffffu, l, o);
        r += __shfl_xor_sync(0xffffffffu, r, o);
    }
    if (lane == 0) {
        g_el[row] = l;
        g_er[row] = r;
        g_eel[row] = __expf(l);
        g_eel2[row] = __expf(ALPHA * l);
        g_eer[row] = __expf(r);
        g_eer2[row] = __expf(ALPHA * r);
    }
}

// ---------------------------------------------------------------------------
extern "C" void kernel_launch(void* const* d_in, const int* in_sizes, int n_in,
                              void* d_out, int out_size)
{
    const float* x   = (const float*)d_in[0];   // (16,1024,256) f32
    const int*   adj = (const int*)d_in[1];     // (16,1024,1024) i32
    const float* W   = (const float*)d_in[2];   // (256,256) f32
    const float* a   = (const float*)d_in[3];   // (512,1) f32
    float* out = (float*)d_out;                 // (16,1024,256) f32

    __half* hT;
    cudaGetSymbolAddress((void**)&hT, g_hT);

    cudaFuncSetAttribute(mma_gemm_kernel,
                         cudaFuncAttributeMaxDynamicSharedMemorySize, G1_SMEM_BYTES);
    cudaFuncSetAttribute(fused_attn_gemm_kernel,
                         cudaFuncAttributeMaxDynamicSharedMemorySize, FU_SMEM_BYTES);

    // 1) wa = W @ [a_l | a_r]   (exact)
    wa_kernel<<<512, 256>>>(W, a);
    // 2) el/er = x @ wa (+ exp precomputes, exact fp32)
    rowdot_x_kernel<<<(NB * NN) / 8, 256>>>(x);
    // 3) hT = fp16(x @ W) transposed  (tf32 mma.sync)
    {
        dim3 grid((NB * NN) / 128, NF / 128, 1);
        mma_gemm_kernel<<<grid, 256, G1_SMEM_BYTES>>>(x, W, hT, NF);
    }
    // 4) out = softmax(mask(leaky(el+er))) @ h — fused fp16 MMA
    {
        dim3 grid(NN / 128, 1, NB);
        fused_attn_gemm_kernel<<<grid, 512, FU_SMEM_BYTES>>>(adj, hT, out);
    }
}

// round 16
// speedup vs baseline: 2.0206x; 1.2165x over previous
#include <cuda_runtime.h>
#include <cuda_fp16.h>
#include <cstdint>

#define ALPHA 0.2f

#define NB 16
#define NN 1024
#define NF 256

// Scratch (device globals: allocation-free rule)
__device__ __half g_hT[NB * NF * NN];         // 8 MB: hT[b][n][m] = fp16(x@W)
__device__ float g_el[NB * NN];
__device__ float g_er[NB * NN];
__device__ float g_eel[NB * NN];              // exp(el)
__device__ float g_eel2[NB * NN];             // exp(ALPHA*el)
__device__ float g_eer[NB * NN];              // exp(er)
__device__ float g_eer2[NB * NN];             // exp(ALPHA*er)
__device__ float g_wa[2 * NF];                // W @ a_l, W @ a_r

// ---------------------------------------------------------------------------
// helpers
// ---------------------------------------------------------------------------
__device__ __forceinline__ uint32_t f2tf32(float f) {
    uint32_t r;
    asm("cvt.rna.tf32.f32 %0, %1;" : "=r"(r) : "f"(f));
    return r;
}
__device__ __forceinline__ void cpasync16(uint32_t dst, const void* src) {
    asm volatile("cp.async.cg.shared.global [%0], [%1], 16;" :: "r"(dst), "l"(src));
}

// ---- GEMM1 (h = x@W, tf32) smem geometry ----
#define AS_STRIDE 36
#define BS_STRIDE 136
#define AS_TILE (128 * AS_STRIDE)      // words
#define BS_TILE (32 * BS_STRIDE)
#define G1_STG (AS_TILE + BS_TILE)
#define G1_SMEM_BYTES (2 * G1_STG * 4)             // 71680

// ---- fused fp16 GEMM smem geometry (bytes), BK=64 ----
// A: 128 rows x 64 halves, stride 144B   -> 18432 B/stage
// B: 256 rows x 64 halves, stride 144B   -> 36864 B/stage
// adj: 128 x 64 int                      -> 32768 B/stage
#define F_STRIDE 144
#define FA_BYTES (128 * F_STRIDE)          // 18432
#define FB_BYTES (256 * F_STRIDE)          // 36864
#define FADJ_BYTES (128 * 64 * 4)          // 32768
#define OFF_FA 0
#define OFF_FB (2 * FA_BYTES)                       // 36864
#define OFF_FADJ (OFF_FB + 2 * FB_BYTES)            // 110592
#define OFF_SROW (OFF_FADJ + 2 * FADJ_BYTES)        // 176128
#define FU_SMEM_BYTES (OFF_SROW + 512)              // 176640

// ---------------------------------------------------------------------------
// GEMM1: h = x@W (tf32 mma.sync, cp.async double-buffered).
// Epilogue writes hT[b][n][m] in fp16 (transposed, for fused B-fragments).
// ---------------------------------------------------------------------------
__global__ __launch_bounds__(256, 2) void mma_gemm_kernel(
    const float* __restrict__ A, const float* __restrict__ B,
    __half* __restrict__ hT, int K)
{
    extern __shared__ float smem[];

    const int lda = K;
    const int ldb = NF;

    const int bm = blockIdx.x * 128;
    const int bn = blockIdx.y * 128;
    const int tid = threadIdx.x;
    const int warp = tid >> 5;
    const int lane = tid & 31;
    const int wm = warp >> 2;
    const int wn = warp & 3;
    const int g = lane >> 2;
    const int t = lane & 3;

    int a_row[4], a_c4[4], b_row[4], b_c4[4];
#pragma unroll
    for (int j = 0; j < 4; j++) {
        int i = tid + j * 256;
        a_row[j] = i >> 3;  a_c4[j] = (i & 7) * 4;
        b_row[j] = i >> 5;  b_c4[j] = (i & 31) * 4;
    }

    uint32_t smem_u32 = (uint32_t)__cvta_generic_to_shared((void*)smem);
    const int niter = K / 32;

    auto issue_stage = [&](int s, int k0) {
        uint32_t as_base = smem_u32 + (uint32_t)(s * G1_STG) * 4u;
        uint32_t bs_base = as_base + (uint32_t)AS_TILE * 4u;
#pragma unroll
        for (int j = 0; j < 4; j++)
            cpasync16(as_base + (uint32_t)(a_row[j] * AS_STRIDE + a_c4[j]) * 4u,
                      &A[(size_t)(bm + a_row[j]) * lda + k0 + a_c4[j]]);
#pragma unroll
        for (int j = 0; j < 4; j++)
            cpasync16(bs_base + (uint32_t)(b_row[j] * BS_STRIDE + b_c4[j]) * 4u,
                      &B[(size_t)(k0 + b_row[j]) * ldb + bn + b_c4[j]]);
        asm volatile("cp.async.commit_group;");
    };

    float acc[4][4][4];
#pragma unroll
    for (int mi = 0; mi < 4; mi++)
#pragma unroll
        for (int ni = 0; ni < 4; ni++)
#pragma unroll
            for (int r = 0; r < 4; r++) acc[mi][ni][r] = 0.f;

    issue_stage(0, 0);

    for (int it = 0; it < niter; it++) {
        if (it + 1 < niter) {
            issue_stage((it + 1) & 1, (it + 1) * 32);
            asm volatile("cp.async.wait_group 1;");
        } else {
            asm volatile("cp.async.wait_group 0;");
        }
        __syncthreads();

        const float* As = smem + (it & 1) * G1_STG;
        const float* Bs = As + AS_TILE;

#pragma unroll
        for (int kc = 0; kc < 4; kc++) {
            const int kk = kc * 8;
            uint32_t af[4][4], bf[4][2];
#pragma unroll
            for (int mi = 0; mi < 4; mi++) {
                int m0 = wm * 64 + mi * 16;
                af[mi][0] = f2tf32(As[(m0 + g) * AS_STRIDE + kk + t]);
                af[mi][1] = f2tf32(As[(m0 + g + 8) * AS_STRIDE + kk + t]);
                af[mi][2] = f2tf32(As[(m0 + g) * AS_STRIDE + kk + t + 4]);
                af[mi][3] = f2tf32(As[(m0 + g + 8) * AS_STRIDE + kk + t + 4]);
            }
#pragma unroll
            for (int ni = 0; ni < 4; ni++) {
                int n0 = wn * 32 + ni * 8;
                bf[ni][0] = f2tf32(Bs[(kk + t) * BS_STRIDE + n0 + g]);
                bf[ni][1] = f2tf32(Bs[(kk + t + 4) * BS_STRIDE + n0 + g]);
            }
#pragma unroll
            for (int mi = 0; mi < 4; mi++)
#pragma unroll
                for (int ni = 0; ni < 4; ni++) {
                    asm volatile(
                        "mma.sync.aligned.m16n8k8.row.col.f32.tf32.tf32.f32 "
                        "{%0,%1,%2,%3}, {%4,%5,%6,%7}, {%8,%9}, {%0,%1,%2,%3};"
                        : "+f"(acc[mi][ni][0]), "+f"(acc[mi][ni][1]),
                          "+f"(acc[mi][ni][2]), "+f"(acc[mi][ni][3])
                        : "r"(af[mi][0]), "r"(af[mi][1]), "r"(af[mi][2]), "r"(af[mi][3]),
                          "r"(bf[ni][0]), "r"(bf[ni][1]));
                }
        }
        __syncthreads();
    }

    // Epilogue: hT[b][n][m] = fp16(acc)
#pragma unroll
    for (int mi = 0; mi < 4; mi++) {
#pragma unroll
        for (int ni = 0; ni < 4; ni++) {
            int row0 = bm + wm * 64 + mi * 16 + g;
            int col = bn + wn * 32 + ni * 8 + t * 2;
            int bi = row0 >> 10, m = row0 & 1023;
            __half* p = hT + ((size_t)bi * NF + col) * NN + m;
            p[0]       = __float2half_rn(acc[mi][ni][0]);
            p[NN]      = __float2half_rn(acc[mi][ni][1]);
            p[8]       = __float2half_rn(acc[mi][ni][2]);
            p[NN + 8]  = __float2half_rn(acc[mi][ni][3]);
        }
    }
}

// ---------------------------------------------------------------------------
// FUSED attention GEMM, fp16 mma.m16n8k16, BK=64, 128x256 tile, 512 threads.
// Fragments via ldmatrix; double buffer; 16 k-iterations.
// ---------------------------------------------------------------------------
__global__ __launch_bounds__(512, 1) void fused_attn_gemm_kernel(
    const int* __restrict__ adjg, const __half* __restrict__ hTg,
    float* __restrict__ Cg)
{
    extern __shared__ char smc[];
    uint32_t sb = (uint32_t)__cvta_generic_to_shared((void*)smc);
    float* srow = (float*)(smc + OFF_SROW);

    const int b = blockIdx.z;
    const int* Aj = adjg + (size_t)b * NN * NN;
    const __half* hTb = hTg + (size_t)b * NF * NN;
    float* C = Cg + (size_t)b * NN * NF;
    const float* er_b = g_er + b * NN;
    const float* eer_b = g_eer + b * NN;
    const float* eer2_b = g_eer2 + b * NN;

    const int bm = blockIdx.x * 128;
    const int tid = threadIdx.x;
    const int warp = tid >> 5;
    const int lane = tid & 31;
    const int wm = warp >> 3;        // 0..1 (M)
    const int wn = warp & 7;         // 0..7 (N)
    const int g = lane >> 2;
    const int t = lane & 3;

    // fill coords: 4 rows (ar4 + 32j), fixed cols ac4..ac4+3
    const int ar4 = tid >> 4;            // 0..31
    const int ac4 = (tid & 15) * 4;      // 0..60
    // B cp coords: 2048 16B-chunks / 512 = 4 each
    int bn_row[4], bn_ch[4];
#pragma unroll
    for (int j = 0; j < 4; j++) {
        int i = tid + j * 512;
        bn_row[j] = i >> 3;  bn_ch[j] = i & 7;
    }

    float elr[4], eelr[4], eel2r[4];
#pragma unroll
    for (int j = 0; j < 4; j++) {
        int row = bm + ar4 + j * 32;
        elr[j] = g_el[b * NN + row];
        eelr[j] = g_eel[b * NN + row];
        eel2r[j] = g_eel2[b * NN + row];
    }
    float psum[4] = {0.f, 0.f, 0.f, 0.f};

    // ldmatrix lane addressing offsets
    const int a_lrow = (lane & 7) + ((lane >> 3) & 1) * 8;   // row within 16
    const int a_lcol = (lane >> 4) * 16;                      // 0 or 16 bytes
    const int b_lrow = lane & 7;
    const int b_lcol = ((lane >> 3) & 1) * 16;                // lanes 0-15 used

    auto issue_cp = [&](int s, int k0) {
        uint32_t aj = sb + OFF_FADJ + (uint32_t)(s * FADJ_BYTES);
#pragma unroll
        for (int j = 0; j < 4; j++) {
            int row = ar4 + j * 32;
            cpasync16(aj + (uint32_t)(row * 64 + ac4) * 4u,
                      Aj + (size_t)(bm + row) * NN + k0 + ac4);
        }
        uint32_t bs = sb + OFF_FB + (uint32_t)(s * FB_BYTES);
#pragma unroll
        for (int j = 0; j < 4; j++)
            cpasync16(bs + (uint32_t)(bn_row[j] * F_STRIDE + bn_ch[j] * 16),
                      hTb + (size_t)bn_row[j] * NN + k0 + bn_ch[j] * 8);
        asm volatile("cp.async.commit_group;");
    };

    float acc[4][4][4];
#pragma unroll
    for (int mi = 0; mi < 4; mi++)
#pragma unroll
        for (int ni = 0; ni < 4; ni++)
#pragma unroll
            for (int r = 0; r < 4; r++) acc[mi][ni][r] = 0.f;

    issue_cp(0, 0);

    const int niter = NN / 64;     // 16
    for (int it = 0; it < niter; it++) {
        const int k0 = it * 64;
        const int s = it & 1;
        if (it + 1 < niter) {
            issue_cp(s ^ 1, (it + 1) * 64);
            asm volatile("cp.async.wait_group 1;");
        } else {
            asm volatile("cp.async.wait_group 0;");
        }
        __syncthreads();

        // ---- fill A-tile: p~ = fp16(sel(adj, Eel*Eer | Eel2*Eer2, 0)) ----
        {
            const int* adjS = (const int*)(smc + OFF_FADJ + s * FADJ_BYTES);
            char* AsB = smc + OFF_FA + s * FA_BYTES;
            float4 er4 = *(const float4*)&er_b[k0 + ac4];
            float4 ee4 = *(const float4*)&eer_b[k0 + ac4];
            float4 ee24 = *(const float4*)&eer2_b[k0 + ac4];
#pragma unroll
            for (int j = 0; j < 4; j++) {
                int row = ar4 + j * 32;
                int4 av = *(const int4*)&adjS[row * 64 + ac4];
                float el_ = elr[j], ee_ = eelr[j], ee2_ = eel2r[j];
                bool s0 = (el_ + er4.x) > 0.f;
                bool s1 = (el_ + er4.y) > 0.f;
                bool s2 = (el_ + er4.z) > 0.f;
                bool s3 = (el_ + er4.w) > 0.f;
                float p0 = av.x > 0 ? (s0 ? ee_ * ee4.x : ee2_ * ee24.x) : 0.f;
                float p1 = av.y > 0 ? (s1 ? ee_ * ee4.y : ee2_ * ee24.y) : 0.f;
                float p2 = av.z > 0 ? (s2 ? ee_ * ee4.z : ee2_ * ee24.z) : 0.f;
                float p3 = av.w > 0 ? (s3 ? ee_ * ee4.w : ee2_ * ee24.w) : 0.f;
                __half2 h01 = __floats2half2_rn(p0, p1);
                __half2 h23 = __floats2half2_rn(p2, p3);
                *(uint2*)(AsB + row * F_STRIDE + ac4 * 2) =
                    make_uint2(*(uint32_t*)&h01, *(uint32_t*)&h23);
                psum[j] += __low2float(h01) + __high2float(h01) +
                           __low2float(h23) + __high2float(h23);
            }
        }
        __syncthreads();

        uint32_t sbA = sb + OFF_FA + (uint32_t)(s * FA_BYTES);
        uint32_t sbB = sb + OFF_FB + (uint32_t)(s * FB_BYTES);

        // ---- 4 ksteps of K=16, fragments via ldmatrix ----
#pragma unroll
        for (int ks = 0; ks < 4; ks++) {
            uint32_t af[4][4], bf[4][2];
#pragma unroll
            for (int mi = 0; mi < 4; mi++) {
                uint32_t addr = sbA + (uint32_t)((wm * 64 + mi * 16 + a_lrow) * F_STRIDE
                                                 + ks * 32 + a_lcol);
                asm volatile(
                    "ldmatrix.sync.aligned.m8n8.x4.shared.b16 {%0,%1,%2,%3}, [%4];"
                    : "=r"(af[mi][0]), "=r"(af[mi][1]), "=r"(af[mi][2]), "=r"(af[mi][3])
                    : "r"(addr));
            }
#pragma unroll
            for (int ni = 0; ni < 4; ni++) {
                uint32_t addr = sbB + (uint32_t)((wn * 32 + ni * 8 + b_lrow) * F_STRIDE
                                                 + ks * 32 + b_lcol);
                asm volatile(
                    "ldmatrix.sync.aligned.m8n8.x2.shared.b16 {%0,%1}, [%2];"
                    : "=r"(bf[ni][0]), "=r"(bf[ni][1])
                    : "r"(addr));
            }
#pragma unroll
            for (int mi = 0; mi < 4; mi++)
#pragma unroll
                for (int ni = 0; ni < 4; ni++) {
                    asm volatile(
                        "mma.sync.aligned.m16n8k16.row.col.f32.f16.f16.f32 "
                        "{%0,%1,%2,%3}, {%4,%5,%6,%7}, {%8,%9}, {%0,%1,%2,%3};"
                        : "+f"(acc[mi][ni][0]), "+f"(acc[mi][ni][1]),
                          "+f"(acc[mi][ni][2]), "+f"(acc[mi][ni][3])
                        : "r"(af[mi][0]), "r"(af[mi][1]), "r"(af[mi][2]), "r"(af[mi][3]),
                          "r"(bf[ni][0]), "r"(bf[ni][1]));
                }
        }
        __syncthreads();
    }

    // Deterministic per-row sum: 16 lanes own each row's fill
#pragma unroll
    for (int j = 0; j < 4; j++) {
        float v = psum[j];
        v += __shfl_xor_sync(0xffffffffu, v, 8);
        v += __shfl_xor_sync(0xffffffffu, v, 4);
        v += __shfl_xor_sync(0xffffffffu, v, 2);
        v += __shfl_xor_sync(0xffffffffu, v, 1);
        if ((lane & 15) == 0) srow[ar4 + j * 32] = v;
    }
    __syncthreads();

#pragma unroll
    for (int mi = 0; mi < 4; mi++) {
        int r0 = wm * 64 + mi * 16 + g;
        float inv0 = 1.0f / srow[r0];
        float inv8 = 1.0f / srow[r0 + 8];
#pragma unroll
        for (int ni = 0; ni < 4; ni++) {
            int col = wn * 32 + ni * 8 + t * 2;
            *(float2*)&C[(size_t)(bm + r0) * NF + col] =
                make_float2(acc[mi][ni][0] * inv0, acc[mi][ni][1] * inv0);
            *(float2*)&C[(size_t)(bm + r0 + 8) * NF + col] =
                make_float2(acc[mi][ni][2] * inv8, acc[mi][ni][3] * inv8);
        }
    }
}

// ---------------------------------------------------------------------------
// wa[sel][i] = sum_o W[i][o] * a[sel*256 + o]    (exact fp32, tiny)
// ---------------------------------------------------------------------------
__global__ __launch_bounds__(256) void wa_kernel(
    const float* __restrict__ W, const float* __restrict__ a)
{
    int i = blockIdx.x & 255;
    int sel = blockIdx.x >> 8;
    int tid = threadIdx.x;
    float v = W[(size_t)i * NF + tid] * a[sel * NF + tid];
#pragma unroll
    for (int off = 16; off > 0; off >>= 1)
        v += __shfl_xor_sync(0xffffffffu, v, off);
    __shared__ float s[8];
    if ((tid & 31) == 0) s[tid >> 5] = v;
    __syncthreads();
    if (tid == 0) {
        float acc = 0.f;
#pragma unroll
        for (int w = 0; w < 8; w++) acc += s[w];
        g_wa[sel * NF + i] = acc;
    }
}

// ---------------------------------------------------------------------------
// Warp-per-row: el/er = x . wa  (float4 loads) + exp precomputes.
// ---------------------------------------------------------------------------
__global__ __launch_bounds__(256) void rowdot_x_kernel(const float* __restrict__ x)
{
    int row = blockIdx.x * 8 + (threadIdx.x >> 5);
    int lane = threadIdx.x & 31;
    const float* xr = x + (size_t)row * NF;

    float l = 0.f, r = 0.f;
#pragma unroll
    for (int c = 0; c < 2; c++) {
        int idx = (lane + c * 32) * 4;
        float4 xv = *(const float4*)&xr[idx];
        float4 wl = *(const float4*)&g_wa[idx];
        float4 wr = *(const float4*)&g_wa[NF + idx];
        l += xv.x * wl.x + xv.y * wl.y + xv.z * wl.z + xv.w * wl.w;
        r += xv.x * wr.x + xv.y * wr.y + xv.z * wr.z + xv.w * wr.w;
    }
#pragma unroll
    for (int o = 16; o > 0; o >>= 1) {
        l += __shfl_xor_sync(0xffffffffu, l, o);
        r += __shfl_xor_sync(0xffffffffu, r, o);
    }
    if (lane == 0) {
        g_el[row] = l;
        g_er[row] = r;
        g_eel[row] = __expf(l);
        g_eel2[row] = __expf(ALPHA * l);
        g_eer[row] = __expf(r);
        g_eer2[row] = __expf(ALPHA * r);
    }
}

// ---------------------------------------------------------------------------
extern "C" void kernel_launch(void* const* d_in, const int* in_sizes, int n_in,
                              void* d_out, int out_size)
{
    const float* x   = (const float*)d_in[0];   // (16,1024,256) f32
    const int*   adj = (const int*)d_in[1];     // (16,1024,1024) i32
    const float* W   = (const float*)d_in[2];   // (256,256) f32
    const float* a   = (const float*)d_in[3];   // (512,1) f32
    float* out = (float*)d_out;                 // (16,1024,256) f32

    __half* hT;
    cudaGetSymbolAddress((void**)&hT, g_hT);

    cudaFuncSetAttribute(mma_gemm_kernel,
                         cudaFuncAttributeMaxDynamicSharedMemorySize, G1_SMEM_BYTES);
    cudaFuncSetAttribute(fused_attn_gemm_kernel,
                         cudaFuncAttributeMaxDynamicSharedMemorySize, FU_SMEM_BYTES);

    // 1) wa = W @ [a_l | a_r]   (exact)
    wa_kernel<<<512, 256>>>(W, a);
    // 2) el/er = x @ wa (+ exp precomputes, exact fp32)
    rowdot_x_kernel<<<(NB * NN) / 8, 256>>>(x);
    // 3) hT = fp16(x @ W) transposed  (tf32 mma.sync)
    {
        dim3 grid((NB * NN) / 128, NF / 128, 1);
        mma_gemm_kernel<<<grid, 256, G1_SMEM_BYTES>>>(x, W, hT, NF);
    }
    // 4) out = softmax(mask(leaky(el+er))) @ h — fused fp16 MMA, BK=64
    {
        dim3 grid(NN / 128, 1, NB);
        fused_attn_gemm_kernel<<<grid, 512, FU_SMEM_BYTES>>>(adj, hT, out);
    }
}

// round 17
// speedup vs baseline: 2.3328x; 1.1546x over previous
#include <cuda_runtime.h>
#include <cuda_fp16.h>
#include <cstdint>

#define ALPHA 0.2f

#define NB 16
#define NN 1024
#define NF 256

// Scratch (device globals: allocation-free rule)
__device__ __half g_hT[NB * NF * NN];         // 8 MB: hT[b][n][m] = fp16(x@W)
__device__ __half g_x16[NB * NN * NF];        // 8 MB: fp16(x)
__device__ __half g_WT[NF * NF];              // 128 KB: WT[n][i] = fp16(W[i][n])
__device__ float g_el[NB * NN];
__device__ float g_er[NB * NN];
__device__ float g_eel[NB * NN];              // exp(el)
__device__ float g_eel2[NB * NN];             // exp(ALPHA*el)
__device__ float g_eer[NB * NN];              // exp(er)
__device__ float g_eer2[NB * NN];             // exp(ALPHA*er)
__device__ float g_wa[2 * NF];                // W @ a_l, W @ a_r

// ---------------------------------------------------------------------------
// helpers
// ---------------------------------------------------------------------------
__device__ __forceinline__ void cpasync16(uint32_t dst, const void* src) {
    asm volatile("cp.async.cg.shared.global [%0], [%1], 16;" :: "r"(dst), "l"(src));
}

// ---- fused fp16 GEMM smem geometry (bytes), BK=64 ----
#define F_STRIDE 144
#define FA_BYTES (128 * F_STRIDE)          // 18432
#define FB_BYTES (256 * F_STRIDE)          // 36864
#define FADJ_BYTES (128 * 64 * 4)          // 32768
#define OFF_FA 0
#define OFF_FB (2 * FA_BYTES)                       // 36864
#define OFF_FADJ (OFF_FB + 2 * FB_BYTES)            // 110592
#define OFF_SROW (OFF_FADJ + 2 * FADJ_BYTES)        // 176128
#define OFF_ER (OFF_SROW + 512)                     // 176640
#define OFF_EER (OFF_ER + 4096)                     // 180736
#define OFF_EER2 (OFF_EER + 4096)                   // 184832
#define FU_SMEM_BYTES (OFF_EER2 + 4096)             // 188928

// ---- GEMM1 fp16 smem geometry ----
#define WT_STRIDE 528                     // 512B row + 16B pad (LDSM conflict-free)
#define OFF_WT 0
#define WT_BYTES (256 * WT_STRIDE)        // 135168
#define OFF_XA WT_BYTES
#define G1_SMEM_BYTES (OFF_XA + 2 * FA_BYTES)       // 172032

// ---------------------------------------------------------------------------
// GEMM1: hT[b][n][m] = fp16(x @ W) — fp16 mma m16n8k16, whole WT in smem,
// x16 tiles double-buffered, BK=64, 4 k-iters, 512 threads (2x8 warps).
// ---------------------------------------------------------------------------
__global__ __launch_bounds__(512, 1) void gemm1_fp16_kernel(
    const __half* __restrict__ x16, const __half* __restrict__ WTg,
    __half* __restrict__ hT)
{
    extern __shared__ char smc[];
    uint32_t sb = (uint32_t)__cvta_generic_to_shared((void*)smc);

    const int bm = blockIdx.x * 128;      // global row 0..16383
    const int tid = threadIdx.x;
    const int warp = tid >> 5;
    const int lane = tid & 31;
    const int wm = warp >> 3;             // 0..1 (M)
    const int wn = warp & 7;              // 0..7 (N)
    const int g = lane >> 2;
    const int t = lane & 3;

    const int a_lrow = (lane & 7) + ((lane >> 3) & 1) * 8;
    const int a_lcol = (lane >> 4) * 16;
    const int b_lrow = lane & 7;
    const int b_lcol = ((lane >> 3) & 1) * 16;

    // Load whole WT (256 x 256 halves) into smem: 8192 16B-chunks / 512 = 16 ea
#pragma unroll
    for (int j = 0; j < 16; j++) {
        int idx = tid + j * 512;
        int n = idx >> 5, ch = idx & 31;
        cpasync16(sb + OFF_WT + (uint32_t)(n * WT_STRIDE + ch * 16),
                  WTg + (size_t)n * NF + ch * 8);
    }
    asm volatile("cp.async.commit_group;");

    // A (x16) tile cp coords: 1024 chunks / 512 = 2 each
    auto issue_A = [&](int s, int k0) {
        uint32_t dst = sb + OFF_XA + (uint32_t)(s * FA_BYTES);
#pragma unroll
        for (int j = 0; j < 2; j++) {
            int idx = tid + j * 512;
            int row = idx >> 3, ch = idx & 7;
            cpasync16(dst + (uint32_t)(row * F_STRIDE + ch * 16),
                      x16 + (size_t)(bm + row) * NF + k0 + ch * 8);
        }
        asm volatile("cp.async.commit_group;");
    };

    float acc[4][4][4];
#pragma unroll
    for (int mi = 0; mi < 4; mi++)
#pragma unroll
        for (int ni = 0; ni < 4; ni++)
#pragma unroll
            for (int r = 0; r < 4; r++) acc[mi][ni][r] = 0.f;

    issue_A(0, 0);

    const int niter = NF / 64;       // 4
    for (int it = 0; it < niter; it++) {
        const int s = it & 1;
        if (it + 1 < niter) {
            issue_A(s ^ 1, (it + 1) * 64);
            asm volatile("cp.async.wait_group 1;");
        } else {
            asm volatile("cp.async.wait_group 0;");
        }
        __syncthreads();

        uint32_t sbA = sb + OFF_XA + (uint32_t)(s * FA_BYTES);
        uint32_t sbB = sb + OFF_WT + (uint32_t)(it * 64 * 2);   // k-offset in bytes

#pragma unroll
        for (int ks = 0; ks < 4; ks++) {
            uint32_t af[4][4], bf[4][2];
#pragma unroll
            for (int mi = 0; mi < 4; mi++) {
                uint32_t addr = sbA + (uint32_t)((wm * 64 + mi * 16 + a_lrow) * F_STRIDE
                                                 + ks * 32 + a_lcol);
                asm volatile(
                    "ldmatrix.sync.aligned.m8n8.x4.shared.b16 {%0,%1,%2,%3}, [%4];"
                    : "=r"(af[mi][0]), "=r"(af[mi][1]), "=r"(af[mi][2]), "=r"(af[mi][3])
                    : "r"(addr));
            }
#pragma unroll
            for (int ni = 0; ni < 4; ni++) {
                uint32_t addr = sbB + (uint32_t)((wn * 32 + ni * 8 + b_lrow) * WT_STRIDE
                                                 + ks * 32 + b_lcol);
                asm volatile(
                    "ldmatrix.sync.aligned.m8n8.x2.shared.b16 {%0,%1}, [%2];"
                    : "=r"(bf[ni][0]), "=r"(bf[ni][1])
                    : "r"(addr));
            }
#pragma unroll
            for (int mi = 0; mi < 4; mi++)
#pragma unroll
                for (int ni = 0; ni < 4; ni++) {
                    asm volatile(
                        "mma.sync.aligned.m16n8k16.row.col.f32.f16.f16.f32 "
                        "{%0,%1,%2,%3}, {%4,%5,%6,%7}, {%8,%9}, {%0,%1,%2,%3};"
                        : "+f"(acc[mi][ni][0]), "+f"(acc[mi][ni][1]),
                          "+f"(acc[mi][ni][2]), "+f"(acc[mi][ni][3])
                        : "r"(af[mi][0]), "r"(af[mi][1]), "r"(af[mi][2]), "r"(af[mi][3]),
                          "r"(bf[ni][0]), "r"(bf[ni][1]));
                }
        }
        __syncthreads();
    }

    // Epilogue: hT[b][n][m] = fp16(acc), transposed store
#pragma unroll
    for (int mi = 0; mi < 4; mi++) {
#pragma unroll
        for (int ni = 0; ni < 4; ni++) {
            int row0 = bm + wm * 64 + mi * 16 + g;
            int col = wn * 32 + ni * 8 + t * 2;
            int bi = row0 >> 10, m = row0 & 1023;
            __half* p = hT + ((size_t)bi * NF + col) * NN + m;
            p[0]      = __float2half_rn(acc[mi][ni][0]);
            p[NN]     = __float2half_rn(acc[mi][ni][1]);
            p[8]      = __float2half_rn(acc[mi][ni][2]);
            p[NN + 8] = __float2half_rn(acc[mi][ni][3]);
        }
    }
}

// ---------------------------------------------------------------------------
// FUSED attention GEMM, fp16 mma.m16n8k16, BK=64, 128x256 tile, 512 threads.
// er/eer/eer2 staged to smem once; fragments via ldmatrix; double buffer.
// ---------------------------------------------------------------------------
__global__ __launch_bounds__(512, 1) void fused_attn_gemm_kernel(
    const int* __restrict__ adjg, const __half* __restrict__ hTg,
    float* __restrict__ Cg)
{
    extern __shared__ char smc[];
    uint32_t sb = (uint32_t)__cvta_generic_to_shared((void*)smc);
    float* srow = (float*)(smc + OFF_SROW);
    float* er_s = (float*)(smc + OFF_ER);
    float* eer_s = (float*)(smc + OFF_EER);
    float* eer2_s = (float*)(smc + OFF_EER2);

    const int b = blockIdx.z;
    const int* Aj = adjg + (size_t)b * NN * NN;
    const __half* hTb = hTg + (size_t)b * NF * NN;
    float* C = Cg + (size_t)b * NN * NF;

    const int bm = blockIdx.x * 128;
    const int tid = threadIdx.x;
    const int warp = tid >> 5;
    const int lane = tid & 31;
    const int wm = warp >> 3;
    const int wn = warp & 7;
    const int g = lane >> 2;
    const int t = lane & 3;

    const int ar4 = tid >> 4;            // 0..31
    const int ac4 = (tid & 15) * 4;      // 0..60
    int bn_row[4], bn_ch[4];
#pragma unroll
    for (int j = 0; j < 4; j++) {
        int i = tid + j * 512;
        bn_row[j] = i >> 3;  bn_ch[j] = i & 7;
    }

    // stage er/eer/eer2 into smem (once)
#pragma unroll
    for (int j = 0; j < 2; j++) {
        int i = tid + j * 512;
        er_s[i]  = g_er[b * NN + i];
        eer_s[i] = g_eer[b * NN + i];
        eer2_s[i] = g_eer2[b * NN + i];
    }

    float elr[4], eelr[4], eel2r[4];
#pragma unroll
    for (int j = 0; j < 4; j++) {
        int row = bm + ar4 + j * 32;
        elr[j] = g_el[b * NN + row];
        eelr[j] = g_eel[b * NN + row];
        eel2r[j] = g_eel2[b * NN + row];
    }
    float psum[4] = {0.f, 0.f, 0.f, 0.f};

    const int a_lrow = (lane & 7) + ((lane >> 3) & 1) * 8;
    const int a_lcol = (lane >> 4) * 16;
    const int b_lrow = lane & 7;
    const int b_lcol = ((lane >> 3) & 1) * 16;

    auto issue_cp = [&](int s, int k0) {
        uint32_t aj = sb + OFF_FADJ + (uint32_t)(s * FADJ_BYTES);
#pragma unroll
        for (int j = 0; j < 4; j++) {
            int row = ar4 + j * 32;
            cpasync16(aj + (uint32_t)(row * 64 + ac4) * 4u,
                      Aj + (size_t)(bm + row) * NN + k0 + ac4);
        }
        uint32_t bs = sb + OFF_FB + (uint32_t)(s * FB_BYTES);
#pragma unroll
        for (int j = 0; j < 4; j++)
            cpasync16(bs + (uint32_t)(bn_row[j] * F_STRIDE + bn_ch[j] * 16),
                      hTb + (size_t)bn_row[j] * NN + k0 + bn_ch[j] * 8);
        asm volatile("cp.async.commit_group;");
    };

    float acc[4][4][4];
#pragma unroll
    for (int mi = 0; mi < 4; mi++)
#pragma unroll
        for (int ni = 0; ni < 4; ni++)
#pragma unroll
            for (int r = 0; r < 4; r++) acc[mi][ni][r] = 0.f;

    issue_cp(0, 0);
    __syncthreads();   // er_s staged (also covered before first use below)

    const int niter = NN / 64;     // 16
    for (int it = 0; it < niter; it++) {
        const int k0 = it * 64;
        const int s = it & 1;
        if (it + 1 < niter) {
            issue_cp(s ^ 1, (it + 1) * 64);
            asm volatile("cp.async.wait_group 1;");
        } else {
            asm volatile("cp.async.wait_group 0;");
        }
        __syncthreads();

        // ---- fill A-tile: p~ = fp16(sel(adj, Eel*Eer | Eel2*Eer2, 0)) ----
        {
            const int* adjS = (const int*)(smc + OFF_FADJ + s * FADJ_BYTES);
            char* AsB = smc + OFF_FA + s * FA_BYTES;
            float4 er4 = *(const float4*)&er_s[k0 + ac4];
            float4 ee4 = *(const float4*)&eer_s[k0 + ac4];
            float4 ee24 = *(const float4*)&eer2_s[k0 + ac4];
#pragma unroll
            for (int j = 0; j < 4; j++) {
                int row = ar4 + j * 32;
                int4 av = *(const int4*)&adjS[row * 64 + ac4];
                float el_ = elr[j], ee_ = eelr[j], ee2_ = eel2r[j];
                bool s0 = (el_ + er4.x) > 0.f;
                bool s1 = (el_ + er4.y) > 0.f;
                bool s2 = (el_ + er4.z) > 0.f;
                bool s3 = (el_ + er4.w) > 0.f;
                float p0 = av.x > 0 ? (s0 ? ee_ * ee4.x : ee2_ * ee24.x) : 0.f;
                float p1 = av.y > 0 ? (s1 ? ee_ * ee4.y : ee2_ * ee24.y) : 0.f;
                float p2 = av.z > 0 ? (s2 ? ee_ * ee4.z : ee2_ * ee24.z) : 0.f;
                float p3 = av.w > 0 ? (s3 ? ee_ * ee4.w : ee2_ * ee24.w) : 0.f;
                __half2 h01 = __floats2half2_rn(p0, p1);
                __half2 h23 = __floats2half2_rn(p2, p3);
                *(uint2*)(AsB + row * F_STRIDE + ac4 * 2) =
                    make_uint2(*(uint32_t*)&h01, *(uint32_t*)&h23);
                psum[j] += __low2float(h01) + __high2float(h01) +
                           __low2float(h23) + __high2float(h23);
            }
        }
        __syncthreads();

        uint32_t sbA = sb + OFF_FA + (uint32_t)(s * FA_BYTES);
        uint32_t sbB = sb + OFF_FB + (uint32_t)(s * FB_BYTES);

        // ---- 4 ksteps of K=16, fragments via ldmatrix ----
#pragma unroll
        for (int ks = 0; ks < 4; ks++) {
            uint32_t af[4][4], bf[4][2];
#pragma unroll
            for (int mi = 0; mi < 4; mi++) {
                uint32_t addr = sbA + (uint32_t)((wm * 64 + mi * 16 + a_lrow) * F_STRIDE
                                                 + ks * 32 + a_lcol);
                asm volatile(
                    "ldmatrix.sync.aligned.m8n8.x4.shared.b16 {%0,%1,%2,%3}, [%4];"
                    : "=r"(af[mi][0]), "=r"(af[mi][1]), "=r"(af[mi][2]), "=r"(af[mi][3])
                    : "r"(addr));
            }
#pragma unroll
            for (int ni = 0; ni < 4; ni++) {
                uint32_t addr = sbB + (uint32_t)((wn * 32 + ni * 8 + b_lrow) * F_STRIDE
                                                 + ks * 32 + b_lcol);
                asm volatile(
                    "ldmatrix.sync.aligned.m8n8.x2.shared.b16 {%0,%1}, [%2];"
                    : "=r"(bf[ni][0]), "=r"(bf[ni][1])
                    : "r"(addr));
            }
#pragma unroll
            for (int mi = 0; mi < 4; mi++)
#pragma unroll
                for (int ni = 0; ni < 4; ni++) {
                    asm volatile(
                        "mma.sync.aligned.m16n8k16.row.col.f32.f16.f16.f32 "
                        "{%0,%1,%2,%3}, {%4,%5,%6,%7}, {%8,%9}, {%0,%1,%2,%3};"
                        : "+f"(acc[mi][ni][0]), "+f"(acc[mi][ni][1]),
                          "+f"(acc[mi][ni][2]), "+f"(acc[mi][ni][3])
                        : "r"(af[mi][0]), "r"(af[mi][1]), "r"(af[mi][2]), "r"(af[mi][3]),
                          "r"(bf[ni][0]), "r"(bf[ni][1]));
                }
        }
        __syncthreads();
    }

    // Deterministic per-row sum: 16 lanes own each row's fill
#pragma unroll
    for (int j = 0; j < 4; j++) {
        float v = psum[j];
        v += __shfl_xor_sync(0xffffffffu, v, 8);
        v += __shfl_xor_sync(0xffffffffu, v, 4);
        v += __shfl_xor_sync(0xffffffffu, v, 2);
        v += __shfl_xor_sync(0xffffffffu, v, 1);
        if ((lane & 15) == 0) srow[ar4 + j * 32] = v;
    }
    __syncthreads();

#pragma unroll
    for (int mi = 0; mi < 4; mi++) {
        int r0 = wm * 64 + mi * 16 + g;
        float inv0 = 1.0f / srow[r0];
        float inv8 = 1.0f / srow[r0 + 8];
#pragma unroll
        for (int ni = 0; ni < 4; ni++) {
            int col = wn * 32 + ni * 8 + t * 2;
            *(float2*)&C[(size_t)(bm + r0) * NF + col] =
                make_float2(acc[mi][ni][0] * inv0, acc[mi][ni][1] * inv0);
            *(float2*)&C[(size_t)(bm + r0 + 8) * NF + col] =
                make_float2(acc[mi][ni][2] * inv8, acc[mi][ni][3] * inv8);
        }
    }
}

// ---------------------------------------------------------------------------
// wa[sel][i] = sum_o W[i][o] * a[sel*256 + o]    (exact fp32, tiny)
// ---------------------------------------------------------------------------
__global__ __launch_bounds__(256) void wa_kernel(
    const float* __restrict__ W, const float* __restrict__ a)
{
    int i = blockIdx.x & 255;
    int sel = blockIdx.x >> 8;
    int tid = threadIdx.x;
    float v = W[(size_t)i * NF + tid] * a[sel * NF + tid];
#pragma unroll
    for (int off = 16; off > 0; off >>= 1)
        v += __shfl_xor_sync(0xffffffffu, v, off);
    __shared__ float s[8];
    if ((tid & 31) == 0) s[tid >> 5] = v;
    __syncthreads();
    if (tid == 0) {
        float acc = 0.f;
#pragma unroll
        for (int w = 0; w < 8; w++) acc += s[w];
        g_wa[sel * NF + i] = acc;
    }
}

// ---------------------------------------------------------------------------
// WT[n][i] = fp16(W[i][n])  (tiny transpose)
// ---------------------------------------------------------------------------
__global__ __launch_bounds__(256) void wt_kernel(const float* __restrict__ W)
{
    int n = blockIdx.x;
    int i = threadIdx.x;
    g_WT[(size_t)n * NF + i] = __float2half_rn(W[(size_t)i * NF + n]);
}

// ---------------------------------------------------------------------------
// Warp-per-row: el/er = x . wa (float4) + exp precomputes + x16 = fp16(x).
// ---------------------------------------------------------------------------
__global__ __launch_bounds__(256) void rowdot_x_kernel(const float* __restrict__ x)
{
    int row = blockIdx.x * 8 + (threadIdx.x >> 5);
    int lane = threadIdx.x & 31;
    const float* xr = x + (size_t)row * NF;
    __half* x16r = g_x16 + (size_t)row * NF;

    float l = 0.f, r = 0.f;
#pragma unroll
    for (int c = 0; c < 2; c++) {
        int idx = (lane + c * 32) * 4;
        float4 xv = *(const float4*)&xr[idx];
        float4 wl = *(const float4*)&g_wa[idx];
        float4 wr = *(const float4*)&g_wa[NF + idx];
        l += xv.x * wl.x + xv.y * wl.y + xv.z * wl.z + xv.w * wl.w;
        r += xv.x * wr.x + xv.y * wr.y + xv.z * wr.z + xv.w * wr.w;
        __half2 h01 = __floats2half2_rn(xv.x, xv.y);
        __half2 h23 = __floats2half2_rn(xv.z, xv.w);
        *(uint2*)&x16r[idx] = make_uint2(*(uint32_t*)&h01, *(uint32_t*)&h23);
    }
#pragma unroll
    for (int o = 16; o > 0; o >>= 1) {
        l += __shfl_xor_sync(0xffffffffu, l, o);
        r += __shfl_xor_sync(0xffffffffu, r, o);
    }
    if (lane == 0) {
        g_el[row] = l;
        g_er[row] = r;
        g_eel[row] = __expf(l);
        g_eel2[row] = __expf(ALPHA * l);
        g_eer[row] = __expf(r);
        g_eer2[row] = __expf(ALPHA * r);
    }
}

// ---------------------------------------------------------------------------
extern "C" void kernel_launch(void* const* d_in, const int* in_sizes, int n_in,
                              void* d_out, int out_size)
{
    const float* x   = (const float*)d_in[0];   // (16,1024,256) f32
    const int*   adj = (const int*)d_in[1];     // (16,1024,1024) i32
    const float* W   = (const float*)d_in[2];   // (256,256) f32
    const float* a   = (const float*)d_in[3];   // (512,1) f32
    float* out = (float*)d_out;                 // (16,1024,256) f32

    __half *hT, *x16, *WT;
    cudaGetSymbolAddress((void**)&hT, g_hT);
    cudaGetSymbolAddress((void**)&x16, g_x16);
    cudaGetSymbolAddress((void**)&WT, g_WT);

    cudaFuncSetAttribute(gemm1_fp16_kernel,
                         cudaFuncAttributeMaxDynamicSharedMemorySize, G1_SMEM_BYTES);
    cudaFuncSetAttribute(fused_attn_gemm_kernel,
                         cudaFuncAttributeMaxDynamicSharedMemorySize, FU_SMEM_BYTES);

    // 1) wa = W @ [a_l | a_r]   (exact)
    wa_kernel<<<512, 256>>>(W, a);
    // 2) WT = fp16(W^T)
    wt_kernel<<<NF, NF>>>(W);
    // 3) el/er = x @ wa (+ exp precomputes) and x16 = fp16(x)
    rowdot_x_kernel<<<(NB * NN) / 8, 256>>>(x);
    // 4) hT = fp16(x @ W) transposed  (fp16 MMA)
    gemm1_fp16_kernel<<<(NB * NN) / 128, 512, G1_SMEM_BYTES>>>(x16, WT, hT);
    // 5) out = softmax(mask(leaky(el+er))) @ h — fused fp16 MMA, BK=64
    {
        dim3 grid(NN / 128, 1, NB);
        fused_attn_gemm_kernel<<<grid, 512, FU_SMEM_BYTES>>>(adj, hT, out);
    }
}